// round 16
// baseline (speedup 1.0000x reference)
#include <cuda_runtime.h>
#include <cstdint>

#define BATCH 8
#define H 128
#define W 128
#define HW (H*W)

typedef unsigned long long u64;
typedef unsigned int u32;

__device__ __forceinline__ u64 pack2(float lo, float hi) {
    u64 r; asm("mov.b64 %0, {%1, %2};" : "=l"(r) : "f"(lo), "f"(hi)); return r;
}
__device__ __forceinline__ u64 dup2(float v) {
    u64 r; asm("mov.b64 %0, {%1, %1};" : "=l"(r) : "f"(v)); return r;
}
__device__ __forceinline__ void unpack2(u64 v, float& lo, float& hi) {
    asm("mov.b64 {%0, %1}, %2;" : "=f"(lo), "=f"(hi) : "l"(v));
}
__device__ __forceinline__ void ffma2(u64& d, u64 a, u64 b) {
    asm("fma.rn.f32x2 %0, %1, %2, %0;" : "+l"(d) : "l"(a), "l"(b));
}
__device__ __forceinline__ void cp16(u32 dst, const void* src) {
    asm volatile("cp.async.ca.shared.global [%0], [%1], 16;" :: "r"(dst), "l"(src) : "memory");
}
__device__ __forceinline__ void cp_commit() {
    asm volatile("cp.async.commit_group;" ::: "memory");
}
__device__ __forceinline__ void cp_wait0() {
    asm volatile("cp.async.wait_group 0;" ::: "memory");
}
__device__ __forceinline__ u32 smem_u32(const void* p) {
    u32 a; asm("{ .reg .u64 t; cvta.to.shared.u64 t, %1; cvt.u32.u64 %0, t; }" : "=r"(a) : "l"(p));
    return a;
}

// ---------------- scratch (device globals; no allocation) ----------------
__device__ float g_cat[BATCH * 128 * HW];
__device__ float g_mix[BATCH * 32  * HW];
__device__ float g_wgt[BATCH * 200 * HW];

__device__ float g_rwT[256 * 128];            // reduce_w transposed [k][oc]
__device__ float g_mixwT[384 * 32];           // conv1/embconv transposed [k][oc]
__device__ float g_mixb[32];
__device__ float g_c2wP[9 * 32 * 12 * 20];    // conv2_w padded [tap][ic][wg12][20] (17 oc/wg)
__device__ float g_owT[128 * 64];             // out_w transposed [c][oc]
__device__ float g_bns[64];
__device__ float g_bnb[64];

// ---------------- prep ----------------
__global__ void prep_kernel(const float* __restrict__ reduce_w,
                            const float* __restrict__ conv1_w, const float* __restrict__ conv1_b,
                            const float* __restrict__ embconv_w, const float* __restrict__ embconv_b,
                            const float* __restrict__ conv2_w,
                            const float* __restrict__ out_w, const float* __restrict__ out_b,
                            const float* __restrict__ bn_gamma, const float* __restrict__ bn_beta,
                            const float* __restrict__ bn_mean, const float* __restrict__ bn_var) {
    int tid = blockIdx.x * blockDim.x + threadIdx.x;
    int nt  = gridDim.x * blockDim.x;
    for (int i = tid; i < 256 * 128; i += nt) {
        int k = i >> 7, oc = i & 127;
        g_rwT[i] = reduce_w[oc * 256 + k];
    }
    for (int i = tid; i < 384 * 32; i += nt) {
        int k = i >> 5, oc = i & 31;
        g_mixwT[i] = (k < 128) ? conv1_w[oc * 128 + k] : embconv_w[oc * 256 + (k - 128)];
    }
    for (int i = tid; i < 32; i += nt) g_mixb[i] = conv1_b[i] + embconv_b[i];
    for (int i = tid; i < 9 * 32 * 12 * 20; i += nt) {
        int tap = i / 7680;
        int r   = i % 7680;
        int ic  = r / 240;
        int r2  = r % 240;
        int wg  = r2 / 20;
        int oo  = r2 % 20;
        int oc  = wg * 17 + oo;
        float v = 0.f;
        if (oo < 17 && oc < 200) v = conv2_w[(oc * 32 + ic) * 9 + tap];
        g_c2wP[i] = v;
    }
    for (int i = tid; i < 128 * 64; i += nt) {
        int c = i >> 6, oc = i & 63;
        g_owT[i] = out_w[oc * 128 + c];
    }
    for (int i = tid; i < 64; i += nt) {
        float s = bn_gamma[i] * rsqrtf(bn_var[i] + 1e-5f);
        g_bns[i] = s;
        g_bnb[i] = bn_beta[i] + (out_b[i] - bn_mean[i]) * s;
    }
}

// ---------------- K1: pixel_shuffle + concat + reduce 1x1 conv ----------------
__global__ void __launch_bounds__(256) k1_cat(const float* __restrict__ hi,
                                              const float* __restrict__ lo,
                                              const float* __restrict__ reduce_b) {
    __shared__ float w2[2][32][128];
    __shared__ float x2[2][32][64];

    u32 w2a = smem_u32(&w2[0][0][0]);

    int p0  = blockIdx.x * 64;
    int b   = p0 / HW;
    int rem = p0 % HW;
    int h   = rem / W;
    int w0  = rem % W;

    int t   = threadIdx.x;
    int ty  = t >> 4, tx = t & 15;
    int oc0 = ty * 8, px0 = tx * 4;

    u64 acc2[4][4];
#pragma unroll
    for (int r = 0; r < 4; r++)
#pragma unroll
        for (int c = 0; c < 4; c++) acc2[r][c] = 0ull;

    {
#pragma unroll
        for (int j = 0; j < 4; j++) {
            int e = t + j * 256;
            cp16(w2a + e * 16, g_rwT + e * 4);
        }
        cp_commit();
        float xr[8];
#pragma unroll
        for (int i = 0; i < 8; i++) {
            int idx = t + i * 256;
            int kk = idx >> 6, px = idx & 63;
            int ww = w0 + px;
            float v;
            if (kk < 32) {
                int ci = kk * 4 + ((h & 1) << 1) + (ww & 1);
                v = hi[((b * 128 + ci) * 64 + (h >> 1)) * 64 + (ww >> 1)];
            } else { v = 0.f; }
            xr[i] = v;
        }
#pragma unroll
        for (int i = 0; i < 8; i++) {
            int idx = t + i * 256;
            x2[0][idx >> 6][idx & 63] = xr[i];
        }
    }

    for (int kc = 0; kc < 8; kc++) {
        cp_wait0();
        __syncthreads();
        float xr[8];
        if (kc < 7) {
            u32 dst = w2a + ((kc + 1) & 1) * 16384;
            const float* wsrc = g_rwT + (kc + 1) * 4096;
#pragma unroll
            for (int j = 0; j < 4; j++) {
                int e = t + j * 256;
                cp16(dst + e * 16, wsrc + e * 4);
            }
            cp_commit();
#pragma unroll
            for (int i = 0; i < 8; i++) {
                int idx = t + i * 256;
                int kk = idx >> 6, px = idx & 63;
                int k  = (kc + 1) * 32 + kk;
                int ww = w0 + px;
                float v;
                if (k < 32) {
                    int ci = k * 4 + ((h & 1) << 1) + (ww & 1);
                    v = hi[((b * 128 + ci) * 64 + (h >> 1)) * 64 + (ww >> 1)];
                } else {
                    v = lo[((b * 224 + (k - 32)) * H + h) * W + ww];
                }
                xr[i] = v;
            }
        }
        int cb = kc & 1;
#pragma unroll
        for (int kk = 0; kk < 32; kk++) {
            ulonglong2 wa = *(const ulonglong2*)&w2[cb][kk][oc0];
            ulonglong2 wb = *(const ulonglong2*)&w2[cb][kk][oc0 + 4];
            float4 bv = *(const float4*)&x2[cb][kk][px0];
            u64 b0 = dup2(bv.x), b1 = dup2(bv.y), b2 = dup2(bv.z), b3 = dup2(bv.w);
            ffma2(acc2[0][0], wa.x, b0); ffma2(acc2[0][1], wa.x, b1);
            ffma2(acc2[0][2], wa.x, b2); ffma2(acc2[0][3], wa.x, b3);
            ffma2(acc2[1][0], wa.y, b0); ffma2(acc2[1][1], wa.y, b1);
            ffma2(acc2[1][2], wa.y, b2); ffma2(acc2[1][3], wa.y, b3);
            ffma2(acc2[2][0], wb.x, b0); ffma2(acc2[2][1], wb.x, b1);
            ffma2(acc2[2][2], wb.x, b2); ffma2(acc2[2][3], wb.x, b3);
            ffma2(acc2[3][0], wb.y, b0); ffma2(acc2[3][1], wb.y, b1);
            ffma2(acc2[3][2], wb.y, b2); ffma2(acc2[3][3], wb.y, b3);
        }
        if (kc < 7) {
            int nb = (kc + 1) & 1;
#pragma unroll
            for (int i = 0; i < 8; i++) {
                int idx = t + i * 256;
                x2[nb][idx >> 6][idx & 63] = xr[i];
            }
        }
    }
#pragma unroll
    for (int r2 = 0; r2 < 4; r2++) {
        int ocA = oc0 + 2 * r2, ocB = ocA + 1;
        float bA = reduce_b[ocA], bB = reduce_b[ocB];
        float4 oa, ob;
        unpack2(acc2[r2][0], oa.x, ob.x);
        unpack2(acc2[r2][1], oa.y, ob.y);
        unpack2(acc2[r2][2], oa.z, ob.z);
        unpack2(acc2[r2][3], oa.w, ob.w);
        oa.x += bA; oa.y += bA; oa.z += bA; oa.w += bA;
        ob.x += bB; ob.y += bB; ob.z += bB; ob.w += bB;
        *(float4*)&g_cat[((b * 128 + ocA) * H + h) * W + w0 + px0] = oa;
        *(float4*)&g_cat[((b * 128 + ocB) * H + h) * W + w0 + px0] = ob;
    }
}

// ---------------- K2: mix = leaky(conv1(cat) + embconv(emb)) ----------------
__global__ void __launch_bounds__(256) k2_mix(const float* __restrict__ emb) {
    __shared__ float w2[2][32][32];
    __shared__ float x2[2][32][128];

    u32 w2a = smem_u32(&w2[0][0][0]);

    int blk = blockIdx.x;
    int b = blk / H, h = blk % H;

    int t   = threadIdx.x;
    int ty  = t >> 5, tx = t & 31;
    int oc0 = ty * 4, px0 = tx * 4;

    u64 acc2[2][4];
#pragma unroll
    for (int r = 0; r < 2; r++)
#pragma unroll
        for (int c = 0; c < 4; c++) acc2[r][c] = 0ull;

    {
        cp16(w2a + t * 16, g_mixwT + t * 4);
        cp_commit();
        float xr[16];
#pragma unroll
        for (int i = 0; i < 16; i++) {
            int idx = t + i * 256;
            int kk = idx >> 7, px = idx & 127;
            xr[i] = g_cat[((b * 128 + kk) * H + h) * W + px];
        }
#pragma unroll
        for (int i = 0; i < 16; i++) {
            int idx = t + i * 256;
            x2[0][idx >> 7][idx & 127] = xr[i];
        }
    }

    for (int kc = 0; kc < 12; kc++) {
        cp_wait0();
        __syncthreads();
        float xr[16];
        if (kc < 11) {
            u32 dst = w2a + ((kc + 1) & 1) * 4096;
            cp16(dst + t * 16, g_mixwT + (kc + 1) * 1024 + t * 4);
            cp_commit();
#pragma unroll
            for (int i = 0; i < 16; i++) {
                int idx = t + i * 256;
                int kk = idx >> 7, px = idx & 127;
                int k  = (kc + 1) * 32 + kk;
                xr[i] = (k < 128)
                    ? g_cat[((b * 128 + k) * H + h) * W + px]
                    : emb[((b * 256 + (k - 128)) * H + h) * W + px];
            }
        }
        int cb = kc & 1;
#pragma unroll
        for (int kk = 0; kk < 32; kk++) {
            ulonglong2 wa = *(const ulonglong2*)&w2[cb][kk][oc0];
            float4 bv = *(const float4*)&x2[cb][kk][px0];
            u64 b0 = dup2(bv.x), b1 = dup2(bv.y), b2 = dup2(bv.z), b3 = dup2(bv.w);
            ffma2(acc2[0][0], wa.x, b0); ffma2(acc2[0][1], wa.x, b1);
            ffma2(acc2[0][2], wa.x, b2); ffma2(acc2[0][3], wa.x, b3);
            ffma2(acc2[1][0], wa.y, b0); ffma2(acc2[1][1], wa.y, b1);
            ffma2(acc2[1][2], wa.y, b2); ffma2(acc2[1][3], wa.y, b3);
        }
        if (kc < 11) {
            int nb = (kc + 1) & 1;
#pragma unroll
            for (int i = 0; i < 16; i++) {
                int idx = t + i * 256;
                x2[nb][idx >> 7][idx & 127] = xr[i];
            }
        }
    }
#pragma unroll
    for (int r2 = 0; r2 < 2; r2++) {
        int ocA = oc0 + 2 * r2, ocB = ocA + 1;
        float bA = g_mixb[ocA], bB = g_mixb[ocB];
        float4 oa, ob;
        unpack2(acc2[r2][0], oa.x, ob.x);
        unpack2(acc2[r2][1], oa.y, ob.y);
        unpack2(acc2[r2][2], oa.z, ob.z);
        unpack2(acc2[r2][3], oa.w, ob.w);
        oa.x += bA; oa.y += bA; oa.z += bA; oa.w += bA;
        ob.x += bB; ob.y += bB; ob.z += bB; ob.w += bB;
        oa.x = oa.x > 0.f ? oa.x : 0.01f * oa.x;
        oa.y = oa.y > 0.f ? oa.y : 0.01f * oa.y;
        oa.z = oa.z > 0.f ? oa.z : 0.01f * oa.z;
        oa.w = oa.w > 0.f ? oa.w : 0.01f * oa.w;
        ob.x = ob.x > 0.f ? ob.x : 0.01f * ob.x;
        ob.y = ob.y > 0.f ? ob.y : 0.01f * ob.y;
        ob.z = ob.z > 0.f ? ob.z : 0.01f * ob.z;
        ob.w = ob.w > 0.f ? ob.w : 0.01f * ob.w;
        *(float4*)&g_mix[((b * 32 + ocA) * H + h) * W + px0] = oa;
        *(float4*)&g_mix[((b * 32 + ocB) * H + h) * W + px0] = ob;
    }
}

// ---------------- K3: conv2 3x3, 32 -> 200 ----------------
// 384 threads, 12 warps x 17 oc x 2 rows; cp.async double-buffered weights.
// dyn smem: x_s 17408 + wbuf 2*30720 = 78848 -> 2 CTAs/SM, 24 warps/SM.
#define K3_SMEM 78848
extern __shared__ char k3s[];
__global__ void __launch_bounds__(384, 2) k3_conv2(const float* __restrict__ c2b) {
    float (*x_s)[32][34] = (float (*)[32][34])k3s;
    float* wbuf = (float*)(k3s + 17408);

    u32 smem_base = smem_u32(k3s);
    u32 wbuf_sm = smem_base + 17408;

    int blk = blockIdx.x;
    int q   = blk & 3;
    int rest = blk >> 2;
    int h2  = rest & 63;
    int b   = rest >> 6;
    int h0  = h2 * 2;
    int w0  = q * 32;

    int t   = threadIdx.x;
    int px  = t & 31;
    int wg  = t >> 5;                 // 0..11
    int oc0 = wg * 17;

    u64 acc2[2][9];
#pragma unroll
    for (int r = 0; r < 2; r++)
#pragma unroll
        for (int o = 0; o < 9; o++) acc2[r][o] = 0ull;

    // prologue: tap 0 weights (7680 floats = 1920 cp16)
#pragma unroll
    for (int j = 0; j < 5; j++) {
        int e = (t + j * 384) * 4;
        cp16(wbuf_sm + e * 4, g_c2wP + e);
    }
    cp_commit();

    // mix halo tile
    for (int i = t; i < 32 * 34; i += 384) {
        int ic  = i / 34;
        int col = i % 34;
        int ww = w0 - 1 + col;
        bool okc = (ww >= 0) && (ww < W);
        const float* base = &g_mix[(b * 32 + ic) * HW + ww];
#pragma unroll
        for (int r = 0; r < 4; r++) {
            int hh = h0 - 1 + r;
            float v = 0.f;
            if (okc && hh >= 0 && hh < H) v = base[hh * W];
            x_s[r][ic][col] = v;
        }
    }

    for (int tap = 0; tap < 9; tap++) {
        cp_wait0();
        __syncthreads();
        if (tap < 8) {
            u32 dst = wbuf_sm + ((tap + 1) & 1) * 30720;
            const float* src = g_c2wP + (tap + 1) * 7680;
#pragma unroll
            for (int j = 0; j < 5; j++) {
                int e = (t + j * 384) * 4;
                cp16(dst + e * 4, src + e);
            }
            cp_commit();
        }
        const float* wsb = wbuf + (tap & 1) * 7680 + wg * 20;
        int ti = tap / 3, tj = tap % 3;
#pragma unroll
        for (int kk = 0; kk < 32; kk++) {
            u64 x0 = dup2(x_s[ti][kk][px + tj]);
            u64 x1 = dup2(x_s[ti + 1][kk][px + tj]);
            const ulonglong2* wp = (const ulonglong2*)(wsb + kk * 240);
            ulonglong2 wv0 = wp[0];
            ulonglong2 wv1 = wp[1];
            ulonglong2 wv2 = wp[2];
            ulonglong2 wv3 = wp[3];
            ulonglong2 wv4 = wp[4];
            ffma2(acc2[0][0], wv0.x, x0); ffma2(acc2[1][0], wv0.x, x1);
            ffma2(acc2[0][1], wv0.y, x0); ffma2(acc2[1][1], wv0.y, x1);
            ffma2(acc2[0][2], wv1.x, x0); ffma2(acc2[1][2], wv1.x, x1);
            ffma2(acc2[0][3], wv1.y, x0); ffma2(acc2[1][3], wv1.y, x1);
            ffma2(acc2[0][4], wv2.x, x0); ffma2(acc2[1][4], wv2.x, x1);
            ffma2(acc2[0][5], wv2.y, x0); ffma2(acc2[1][5], wv2.y, x1);
            ffma2(acc2[0][6], wv3.x, x0); ffma2(acc2[1][6], wv3.x, x1);
            ffma2(acc2[0][7], wv3.y, x0); ffma2(acc2[1][7], wv3.y, x1);
            ffma2(acc2[0][8], wv4.x, x0); ffma2(acc2[1][8], wv4.x, x1);
        }
    }
#pragma unroll
    for (int o2 = 0; o2 < 9; o2++) {
        int ocA = oc0 + 2 * o2;
        bool okA = (2 * o2 < 17) && (ocA < 200);
        bool okB = (2 * o2 + 1 < 17) && (ocA + 1 < 200);
        float bA = okA ? c2b[ocA] : 0.f;
        float bB = okB ? c2b[ocA + 1] : 0.f;
#pragma unroll
        for (int r = 0; r < 2; r++) {
            float lo, hi;
            unpack2(acc2[r][o2], lo, hi);
            if (okA)
                g_wgt[((b * 200 + ocA) * H + (h0 + r)) * W + w0 + px] = lo + bA;
            if (okB)
                g_wgt[((b * 200 + ocA + 1) * H + (h0 + r)) * W + w0 + px] = hi + bB;
        }
    }
}

// ---------------- K4: involution + out conv + BN + leaky ----------------
#define K4_SMEM 78592
extern __shared__ char k4s[];
__global__ void __launch_bounds__(256) k4_out(float* __restrict__ out) {
    u64   (*c2)[8][5][36] = (u64 (*)[8][5][36])k4s;
    float (*w2)[25][32]   = (float (*)[25][32])(k4s + 23040);
    float (*o_s)[32]      = (float (*)[32])(k4s + 29440);
    float (*ow_s)[64]     = (float (*)[64])(k4s + 45824);

    int blk = blockIdx.x;
    int q   = blk & 3;
    int h   = (blk >> 2) & 127;
    int b   = blk >> 9;
    int w0  = q * 32;

    int t  = threadIdx.x;
    int px = t & 31;
    int tg = t >> 5;

    {
        u32 owsm = smem_u32(k4s) + 45824;
#pragma unroll
        for (int j = 0; j < 8; j++) {
            int e = t + j * 256;
            cp16(owsm + e * 16, g_owT + e * 4);
        }
        cp_commit();
    }

    int ccA = t / 36,         colA = t % 36;
    int ccB = (t + 256) / 36, colB = (t + 256) % 36;
    bool hasB = (t < 32);
    int wwA = w0 - 2 + colA;  bool okA = (wwA >= 0) && (wwA < W);
    int wwB = w0 - 2 + colB;  bool okB = (wwB >= 0) && (wwB < W);
    bool hasW3 = (t < 32);

    float pa[5][2], pb[5][2], pw[4];

    {
        const float* baseA = &g_cat[(b * 128 + ccA) * HW + wwA];
#pragma unroll
        for (int rr = 0; rr < 5; rr++) {
            int hh = h - 2 + rr;
            bool ok = okA && hh >= 0 && hh < H;
            pa[rr][0] = ok ? baseA[hh * W] : 0.f;
            pa[rr][1] = ok ? baseA[8 * HW + hh * W] : 0.f;
        }
        if (hasB) {
            const float* baseB = &g_cat[(b * 128 + ccB) * HW + wwB];
#pragma unroll
            for (int rr = 0; rr < 5; rr++) {
                int hh = h - 2 + rr;
                bool ok = okB && hh >= 0 && hh < H;
                pb[rr][0] = ok ? baseB[hh * W] : 0.f;
                pb[rr][1] = ok ? baseB[8 * HW + hh * W] : 0.f;
            }
        }
        const float* wbase = &g_wgt[((u64)(b * 200) * H + h) * W + w0];
#pragma unroll
        for (int j = 0; j < 3; j++) {
            int i = t + j * 256;
            pw[j] = wbase[(u64)(i >> 5) * HW + (i & 31)];
        }
        if (hasW3) {
            int i = t + 768;
            pw[3] = wbase[(u64)(i >> 5) * HW + (i & 31)];
        }
#pragma unroll
        for (int rr = 0; rr < 5; rr++) c2[0][ccA][rr][colA] = pack2(pa[rr][0], pa[rr][1]);
        if (hasB)
#pragma unroll
            for (int rr = 0; rr < 5; rr++) c2[0][ccB][rr][colB] = pack2(pb[rr][0], pb[rr][1]);
#pragma unroll
        for (int j = 0; j < 3; j++) {
            int i = t + j * 256;
            w2[0][i >> 5][i & 31] = pw[j];
        }
        if (hasW3) {
            int i = t + 768;
            w2[0][i >> 5][i & 31] = pw[3];
        }
    }

    for (int g = 0; g < 8; g++) {
        __syncthreads();
        if (g < 7) {
            int gc = (g + 1) * 16;
            const float* baseA = &g_cat[(b * 128 + gc + ccA) * HW + wwA];
#pragma unroll
            for (int rr = 0; rr < 5; rr++) {
                int hh = h - 2 + rr;
                bool ok = okA && hh >= 0 && hh < H;
                pa[rr][0] = ok ? baseA[hh * W] : 0.f;
                pa[rr][1] = ok ? baseA[8 * HW + hh * W] : 0.f;
            }
            if (hasB) {
                const float* baseB = &g_cat[(b * 128 + gc + ccB) * HW + wwB];
#pragma unroll
                for (int rr = 0; rr < 5; rr++) {
                    int hh = h - 2 + rr;
                    bool ok = okB && hh >= 0 && hh < H;
                    pb[rr][0] = ok ? baseB[hh * W] : 0.f;
                    pb[rr][1] = ok ? baseB[8 * HW + hh * W] : 0.f;
                }
            }
            const float* wbase = &g_wgt[((u64)(b * 200 + (g + 1) * 25) * H + h) * W + w0];
#pragma unroll
            for (int j = 0; j < 3; j++) {
                int i = t + j * 256;
                pw[j] = wbase[(u64)(i >> 5) * HW + (i & 31)];
            }
            if (hasW3) {
                int i = t + 768;
                pw[3] = wbase[(u64)(i >> 5) * HW + (i & 31)];
            }
        }
        int cb = g & 1;
        u64 a = 0ull;
#pragma unroll
        for (int i = 0; i < 5; i++)
#pragma unroll
            for (int j = 0; j < 5; j++) {
                u64 wv = dup2(w2[cb][i * 5 + j][px]);
                ffma2(a, c2[cb][tg][i][px + j], wv);
            }
        float lo, hi;
        unpack2(a, lo, hi);
        o_s[g * 16 + tg][px]     = lo;
        o_s[g * 16 + tg + 8][px] = hi;
        if (g < 7) {
            int nb = (g + 1) & 1;
#pragma unroll
            for (int rr = 0; rr < 5; rr++) c2[nb][ccA][rr][colA] = pack2(pa[rr][0], pa[rr][1]);
            if (hasB)
#pragma unroll
                for (int rr = 0; rr < 5; rr++) c2[nb][ccB][rr][colB] = pack2(pb[rr][0], pb[rr][1]);
#pragma unroll
            for (int j = 0; j < 3; j++) {
                int i = t + j * 256;
                w2[nb][i >> 5][i & 31] = pw[j];
            }
            if (hasW3) {
                int i = t + 768;
                w2[nb][i >> 5][i & 31] = pw[3];
            }
        }
    }
    cp_wait0();
    __syncthreads();

    int oc0 = tg * 8;
    u64 acc2[4] = {0ull, 0ull, 0ull, 0ull};
#pragma unroll 4
    for (int c = 0; c < 128; c++) {
        u64 od = dup2(o_s[c][px]);
        ulonglong2 wa = *(const ulonglong2*)&ow_s[c][oc0];
        ulonglong2 wb = *(const ulonglong2*)&ow_s[c][oc0 + 4];
        ffma2(acc2[0], wa.x, od);
        ffma2(acc2[1], wa.y, od);
        ffma2(acc2[2], wb.x, od);
        ffma2(acc2[3], wb.y, od);
    }
#pragma unroll
    for (int i = 0; i < 4; i++) {
        float lo, hi;
        unpack2(acc2[i], lo, hi);
        int ocA = oc0 + 2 * i, ocB = ocA + 1;
        float yA = lo * g_bns[ocA] + g_bnb[ocA];
        float yB = hi * g_bns[ocB] + g_bnb[ocB];
        yA = yA > 0.f ? yA : 0.01f * yA;
        yB = yB > 0.f ? yB : 0.01f * yB;
        out[((b * 64 + ocA) * H + h) * W + w0 + px] = yA;
        out[((b * 64 + ocB) * H + h) * W + w0 + px] = yB;
    }
}

// ---------------- launch ----------------
extern "C" void kernel_launch(void* const* d_in, const int* in_sizes, int n_in,
                              void* d_out, int out_size) {
    const float* hi        = (const float*)d_in[0];
    const float* lo        = (const float*)d_in[1];
    const float* emb       = (const float*)d_in[2];
    const float* reduce_w  = (const float*)d_in[3];
    const float* reduce_b  = (const float*)d_in[4];
    const float* conv1_w   = (const float*)d_in[5];
    const float* conv1_b   = (const float*)d_in[6];
    const float* conv2_w   = (const float*)d_in[7];
    const float* conv2_b   = (const float*)d_in[8];
    const float* embconv_w = (const float*)d_in[9];
    const float* embconv_b = (const float*)d_in[10];
    const float* out_w     = (const float*)d_in[11];
    const float* out_b     = (const float*)d_in[12];
    const float* bn_gamma  = (const float*)d_in[13];
    const float* bn_beta   = (const float*)d_in[14];
    const float* bn_mean   = (const float*)d_in[15];
    const float* bn_var    = (const float*)d_in[16];
    float* out = (float*)d_out;

    cudaFuncSetAttribute(k3_conv2, cudaFuncAttributeMaxDynamicSharedMemorySize, K3_SMEM);
    cudaFuncSetAttribute(k4_out,   cudaFuncAttributeMaxDynamicSharedMemorySize, K4_SMEM);

    prep_kernel<<<128, 256>>>(reduce_w, conv1_w, conv1_b, embconv_w, embconv_b,
                              conv2_w, out_w, out_b, bn_gamma, bn_beta, bn_mean, bn_var);
    k1_cat<<<(BATCH * HW) / 64, 256>>>(hi, lo, reduce_b);
    k2_mix<<<BATCH * H, 256>>>(emb);
    k3_conv2<<<BATCH * (H / 2) * 4, 384, K3_SMEM>>>(conv2_b);
    k4_out<<<BATCH * H * 4, 256, K4_SMEM>>>(out);
}

// round 17
// speedup vs baseline: 1.0310x; 1.0310x over previous
#include <cuda_runtime.h>
#include <cstdint>

#define BATCH 8
#define H 128
#define W 128
#define HW (H*W)

typedef unsigned long long u64;
typedef unsigned int u32;

__device__ __forceinline__ u64 pack2(float lo, float hi) {
    u64 r; asm("mov.b64 %0, {%1, %2};" : "=l"(r) : "f"(lo), "f"(hi)); return r;
}
__device__ __forceinline__ u64 dup2(float v) {
    u64 r; asm("mov.b64 %0, {%1, %1};" : "=l"(r) : "f"(v)); return r;
}
__device__ __forceinline__ void unpack2(u64 v, float& lo, float& hi) {
    asm("mov.b64 {%0, %1}, %2;" : "=f"(lo), "=f"(hi) : "l"(v));
}
__device__ __forceinline__ void ffma2(u64& d, u64 a, u64 b) {
    asm("fma.rn.f32x2 %0, %1, %2, %0;" : "+l"(d) : "l"(a), "l"(b));
}
__device__ __forceinline__ void cp16(u32 dst, const void* src) {
    asm volatile("cp.async.ca.shared.global [%0], [%1], 16;" :: "r"(dst), "l"(src) : "memory");
}
__device__ __forceinline__ void cp_commit() {
    asm volatile("cp.async.commit_group;" ::: "memory");
}
__device__ __forceinline__ void cp_wait0() {
    asm volatile("cp.async.wait_group 0;" ::: "memory");
}
__device__ __forceinline__ u32 smem_u32(const void* p) {
    u32 a; asm("{ .reg .u64 t; cvta.to.shared.u64 t, %1; cvt.u32.u64 %0, t; }" : "=r"(a) : "l"(p));
    return a;
}

// ---------------- scratch (device globals; no allocation) ----------------
__device__ float g_cat[BATCH * 128 * HW];
__device__ float g_mix[BATCH * 32  * HW];
__device__ float g_wgt[BATCH * 200 * HW];

__device__ float g_rwT[256 * 128];            // reduce_w transposed [k][oc]
__device__ float g_mixwT[384 * 32];           // conv1/embconv transposed [k][oc]
__device__ float g_mixb[32];
__device__ float g_c2wP[9 * 32 * 8 * 28];     // conv2_w padded [tap][ic][ocg][28]
__device__ float g_owT[128 * 64];             // out_w transposed [c][oc]
__device__ float g_bns[64];
__device__ float g_bnb[64];

// ---------------- prep ----------------
__global__ void prep_kernel(const float* __restrict__ reduce_w,
                            const float* __restrict__ conv1_w, const float* __restrict__ conv1_b,
                            const float* __restrict__ embconv_w, const float* __restrict__ embconv_b,
                            const float* __restrict__ conv2_w,
                            const float* __restrict__ out_w, const float* __restrict__ out_b,
                            const float* __restrict__ bn_gamma, const float* __restrict__ bn_beta,
                            const float* __restrict__ bn_mean, const float* __restrict__ bn_var) {
    int tid = blockIdx.x * blockDim.x + threadIdx.x;
    int nt  = gridDim.x * blockDim.x;
    for (int i = tid; i < 256 * 128; i += nt) {
        int k = i >> 7, oc = i & 127;
        g_rwT[i] = reduce_w[oc * 256 + k];
    }
    for (int i = tid; i < 384 * 32; i += nt) {
        int k = i >> 5, oc = i & 31;
        g_mixwT[i] = (k < 128) ? conv1_w[oc * 128 + k] : embconv_w[oc * 256 + (k - 128)];
    }
    for (int i = tid; i < 32; i += nt) g_mixb[i] = conv1_b[i] + embconv_b[i];
    for (int i = tid; i < 9 * 32 * 8 * 28; i += nt) {
        int tap = i / 7168;
        int r   = i % 7168;
        int ic  = r / 224;
        int r2  = r % 224;
        int og  = r2 / 28;
        int oo  = r2 % 28;
        float v = 0.f;
        if (oo < 25) v = conv2_w[((og * 25 + oo) * 32 + ic) * 9 + tap];
        g_c2wP[i] = v;
    }
    for (int i = tid; i < 128 * 64; i += nt) {
        int c = i >> 6, oc = i & 63;
        g_owT[i] = out_w[oc * 128 + c];
    }
    for (int i = tid; i < 64; i += nt) {
        float s = bn_gamma[i] * rsqrtf(bn_var[i] + 1e-5f);
        g_bns[i] = s;
        g_bnb[i] = bn_beta[i] + (out_b[i] - bn_mean[i]) * s;
    }
}

// ---------------- K1: pixel_shuffle + concat + reduce 1x1 conv ----------------
// in-loop x staging vectorized (k>=32 is always contiguous lo rows)
__global__ void __launch_bounds__(256) k1_cat(const float* __restrict__ hi,
                                              const float* __restrict__ lo,
                                              const float* __restrict__ reduce_b) {
    __shared__ float w2[2][32][128];
    __shared__ float x2[2][32][64];

    u32 w2a = smem_u32(&w2[0][0][0]);

    int p0  = blockIdx.x * 64;
    int b   = p0 / HW;
    int rem = p0 % HW;
    int h   = rem / W;
    int w0  = rem % W;            // 0 or 64 -> float4 aligned

    int t   = threadIdx.x;
    int ty  = t >> 4, tx = t & 15;
    int oc0 = ty * 8, px0 = tx * 4;

    u64 acc2[4][4];
#pragma unroll
    for (int r = 0; r < 4; r++)
#pragma unroll
        for (int c = 0; c < 4; c++) acc2[r][c] = 0ull;

    {
#pragma unroll
        for (int j = 0; j < 4; j++) {
            int e = t + j * 256;
            cp16(w2a + e * 16, g_rwT + e * 4);
        }
        cp_commit();
        float xr[8];
#pragma unroll
        for (int i = 0; i < 8; i++) {
            int idx = t + i * 256;
            int kk = idx >> 6, px = idx & 63;
            int ww = w0 + px;
            float v;
            if (kk < 32) {
                int ci = kk * 4 + ((h & 1) << 1) + (ww & 1);
                v = hi[((b * 128 + ci) * 64 + (h >> 1)) * 64 + (ww >> 1)];
            } else { v = 0.f; }
            xr[i] = v;
        }
#pragma unroll
        for (int i = 0; i < 8; i++) {
            int idx = t + i * 256;
            x2[0][idx >> 6][idx & 63] = xr[i];
        }
    }

    for (int kc = 0; kc < 8; kc++) {
        cp_wait0();
        __syncthreads();
        float4 xr4[2];
        int kkA = 0, c4A = 0, kkB = 0, c4B = 0;
        if (kc < 7) {
            u32 dst = w2a + ((kc + 1) & 1) * 16384;
            const float* wsrc = g_rwT + (kc + 1) * 4096;
#pragma unroll
            for (int j = 0; j < 4; j++) {
                int e = t + j * 256;
                cp16(dst + e * 16, wsrc + e * 4);
            }
            cp_commit();
            // vectorized x staging: 512 float4, 2 per thread; k>=32 always
#pragma unroll
            for (int i = 0; i < 2; i++) {
                int idx = t + i * 256;
                int kk = idx >> 4, c4 = idx & 15;
                int k  = (kc + 1) * 32 + kk;
                const float* src = &lo[((b * 224 + (k - 32)) * H + h) * W + w0 + c4 * 4];
                xr4[i] = *(const float4*)src;
                if (i == 0) { kkA = kk; c4A = c4; } else { kkB = kk; c4B = c4; }
            }
        }
        int cb = kc & 1;
#pragma unroll
        for (int kk = 0; kk < 32; kk++) {
            ulonglong2 wa = *(const ulonglong2*)&w2[cb][kk][oc0];
            ulonglong2 wb = *(const ulonglong2*)&w2[cb][kk][oc0 + 4];
            float4 bv = *(const float4*)&x2[cb][kk][px0];
            u64 b0 = dup2(bv.x), b1 = dup2(bv.y), b2 = dup2(bv.z), b3 = dup2(bv.w);
            ffma2(acc2[0][0], wa.x, b0); ffma2(acc2[0][1], wa.x, b1);
            ffma2(acc2[0][2], wa.x, b2); ffma2(acc2[0][3], wa.x, b3);
            ffma2(acc2[1][0], wa.y, b0); ffma2(acc2[1][1], wa.y, b1);
            ffma2(acc2[1][2], wa.y, b2); ffma2(acc2[1][3], wa.y, b3);
            ffma2(acc2[2][0], wb.x, b0); ffma2(acc2[2][1], wb.x, b1);
            ffma2(acc2[2][2], wb.x, b2); ffma2(acc2[2][3], wb.x, b3);
            ffma2(acc2[3][0], wb.y, b0); ffma2(acc2[3][1], wb.y, b1);
            ffma2(acc2[3][2], wb.y, b2); ffma2(acc2[3][3], wb.y, b3);
        }
        if (kc < 7) {
            int nb = (kc + 1) & 1;
            *(float4*)&x2[nb][kkA][c4A * 4] = xr4[0];
            *(float4*)&x2[nb][kkB][c4B * 4] = xr4[1];
        }
    }
#pragma unroll
    for (int r2 = 0; r2 < 4; r2++) {
        int ocA = oc0 + 2 * r2, ocB = ocA + 1;
        float bA = reduce_b[ocA], bB = reduce_b[ocB];
        float4 oa, ob;
        unpack2(acc2[r2][0], oa.x, ob.x);
        unpack2(acc2[r2][1], oa.y, ob.y);
        unpack2(acc2[r2][2], oa.z, ob.z);
        unpack2(acc2[r2][3], oa.w, ob.w);
        oa.x += bA; oa.y += bA; oa.z += bA; oa.w += bA;
        ob.x += bB; ob.y += bB; ob.z += bB; ob.w += bB;
        *(float4*)&g_cat[((b * 128 + ocA) * H + h) * W + w0 + px0] = oa;
        *(float4*)&g_cat[((b * 128 + ocB) * H + h) * W + w0 + px0] = ob;
    }
}

// ---------------- K2: mix = leaky(conv1(cat) + embconv(emb)) ----------------
// x staging fully vectorized (float4)
__global__ void __launch_bounds__(256) k2_mix(const float* __restrict__ emb) {
    __shared__ float w2[2][32][32];
    __shared__ float x2[2][32][128];

    u32 w2a = smem_u32(&w2[0][0][0]);

    int blk = blockIdx.x;
    int b = blk / H, h = blk % H;

    int t   = threadIdx.x;
    int ty  = t >> 5, tx = t & 31;
    int oc0 = ty * 4, px0 = tx * 4;

    u64 acc2[2][4];
#pragma unroll
    for (int r = 0; r < 2; r++)
#pragma unroll
        for (int c = 0; c < 4; c++) acc2[r][c] = 0ull;

    {
        cp16(w2a + t * 16, g_mixwT + t * 4);
        cp_commit();
        // kc=0: all rows from g_cat, vectorized
#pragma unroll
        for (int i = 0; i < 4; i++) {
            int idx = t + i * 256;
            int kk = idx >> 5, c4 = idx & 31;
            float4 v = *(const float4*)&g_cat[((b * 128 + kk) * H + h) * W + c4 * 4];
            *(float4*)&x2[0][kk][c4 * 4] = v;
        }
    }

    for (int kc = 0; kc < 12; kc++) {
        cp_wait0();
        __syncthreads();
        float4 xr4[4];
        if (kc < 11) {
            u32 dst = w2a + ((kc + 1) & 1) * 4096;
            cp16(dst + t * 16, g_mixwT + (kc + 1) * 1024 + t * 4);
            cp_commit();
#pragma unroll
            for (int i = 0; i < 4; i++) {
                int idx = t + i * 256;
                int kk = idx >> 5, c4 = idx & 31;
                int k  = (kc + 1) * 32 + kk;
                const float* src = (k < 128)
                    ? &g_cat[((b * 128 + k) * H + h) * W + c4 * 4]
                    : &emb[((b * 256 + (k - 128)) * H + h) * W + c4 * 4];
                xr4[i] = *(const float4*)src;
            }
        }
        int cb = kc & 1;
#pragma unroll
        for (int kk = 0; kk < 32; kk++) {
            ulonglong2 wa = *(const ulonglong2*)&w2[cb][kk][oc0];
            float4 bv = *(const float4*)&x2[cb][kk][px0];
            u64 b0 = dup2(bv.x), b1 = dup2(bv.y), b2 = dup2(bv.z), b3 = dup2(bv.w);
            ffma2(acc2[0][0], wa.x, b0); ffma2(acc2[0][1], wa.x, b1);
            ffma2(acc2[0][2], wa.x, b2); ffma2(acc2[0][3], wa.x, b3);
            ffma2(acc2[1][0], wa.y, b0); ffma2(acc2[1][1], wa.y, b1);
            ffma2(acc2[1][2], wa.y, b2); ffma2(acc2[1][3], wa.y, b3);
        }
        if (kc < 11) {
            int nb = (kc + 1) & 1;
#pragma unroll
            for (int i = 0; i < 4; i++) {
                int idx = t + i * 256;
                int kk = idx >> 5, c4 = idx & 31;
                *(float4*)&x2[nb][kk][c4 * 4] = xr4[i];
            }
        }
    }
#pragma unroll
    for (int r2 = 0; r2 < 2; r2++) {
        int ocA = oc0 + 2 * r2, ocB = ocA + 1;
        float bA = g_mixb[ocA], bB = g_mixb[ocB];
        float4 oa, ob;
        unpack2(acc2[r2][0], oa.x, ob.x);
        unpack2(acc2[r2][1], oa.y, ob.y);
        unpack2(acc2[r2][2], oa.z, ob.z);
        unpack2(acc2[r2][3], oa.w, ob.w);
        oa.x += bA; oa.y += bA; oa.z += bA; oa.w += bA;
        ob.x += bB; ob.y += bB; ob.z += bB; ob.w += bB;
        oa.x = oa.x > 0.f ? oa.x : 0.01f * oa.x;
        oa.y = oa.y > 0.f ? oa.y : 0.01f * oa.y;
        oa.z = oa.z > 0.f ? oa.z : 0.01f * oa.z;
        oa.w = oa.w > 0.f ? oa.w : 0.01f * oa.w;
        ob.x = ob.x > 0.f ? ob.x : 0.01f * ob.x;
        ob.y = ob.y > 0.f ? ob.y : 0.01f * ob.y;
        ob.z = ob.z > 0.f ? ob.z : 0.01f * ob.z;
        ob.w = ob.w > 0.f ? ob.w : 0.01f * ob.w;
        *(float4*)&g_mix[((b * 32 + ocA) * H + h) * W + px0] = oa;
        *(float4*)&g_mix[((b * 32 + ocB) * H + h) * W + px0] = ob;
    }
}

// ---------------- K3: conv2 3x3, 32 -> 200  (R15 proven config, 323.7us) ----------------
#define K3_SMEM 74752
extern __shared__ char k3s[];
__global__ void __launch_bounds__(256, 2) k3_conv2(const float* __restrict__ c2b) {
    float (*x_s)[32][34] = (float (*)[32][34])k3s;
    float* wbuf = (float*)(k3s + 17408);

    u32 smem_base = smem_u32(k3s);
    u32 wbuf_sm = smem_base + 17408;

    int blk = blockIdx.x;
    int q   = blk & 3;
    int rest = blk >> 2;
    int h2  = rest & 63;
    int b   = rest >> 6;
    int h0  = h2 * 2;
    int w0  = q * 32;

    int t   = threadIdx.x;
    int px  = t & 31;
    int ocg = t >> 5;
    int oc0 = ocg * 25;

    u64 acc2[2][13];
#pragma unroll
    for (int r = 0; r < 2; r++)
#pragma unroll
        for (int o = 0; o < 13; o++) acc2[r][o] = 0ull;

#pragma unroll
    for (int j = 0; j < 7; j++) {
        int e = (t + j * 256) * 4;
        cp16(wbuf_sm + e * 4, g_c2wP + e);
    }
    cp_commit();

    for (int i = t; i < 32 * 34; i += 256) {
        int ic  = i / 34;
        int col = i % 34;
        int ww = w0 - 1 + col;
        bool okc = (ww >= 0) && (ww < W);
        const float* base = &g_mix[(b * 32 + ic) * HW + ww];
#pragma unroll
        for (int r = 0; r < 4; r++) {
            int hh = h0 - 1 + r;
            float v = 0.f;
            if (okc && hh >= 0 && hh < H) v = base[hh * W];
            x_s[r][ic][col] = v;
        }
    }

    for (int tap = 0; tap < 9; tap++) {
        cp_wait0();
        __syncthreads();
        if (tap < 8) {
            u32 dst = wbuf_sm + ((tap + 1) & 1) * 28672;
            const float* src = g_c2wP + (tap + 1) * 7168;
#pragma unroll
            for (int j = 0; j < 7; j++) {
                int e = (t + j * 256) * 4;
                cp16(dst + e * 4, src + e);
            }
            cp_commit();
        }
        const float* wsb = wbuf + (tap & 1) * 7168 + ocg * 28;
        int ti = tap / 3, tj = tap % 3;
#pragma unroll
        for (int kk = 0; kk < 32; kk++) {
            u64 x0 = dup2(x_s[ti][kk][px + tj]);
            u64 x1 = dup2(x_s[ti + 1][kk][px + tj]);
            const ulonglong2* wp = (const ulonglong2*)(wsb + kk * 224);
            ulonglong2 wv0 = wp[0];
            ulonglong2 wv1 = wp[1];
            ulonglong2 wv2 = wp[2];
            ulonglong2 wv3 = wp[3];
            ulonglong2 wv4 = wp[4];
            ulonglong2 wv5 = wp[5];
            ulonglong2 wv6 = wp[6];
            ffma2(acc2[0][0],  wv0.x, x0); ffma2(acc2[1][0],  wv0.x, x1);
            ffma2(acc2[0][1],  wv0.y, x0); ffma2(acc2[1][1],  wv0.y, x1);
            ffma2(acc2[0][2],  wv1.x, x0); ffma2(acc2[1][2],  wv1.x, x1);
            ffma2(acc2[0][3],  wv1.y, x0); ffma2(acc2[1][3],  wv1.y, x1);
            ffma2(acc2[0][4],  wv2.x, x0); ffma2(acc2[1][4],  wv2.x, x1);
            ffma2(acc2[0][5],  wv2.y, x0); ffma2(acc2[1][5],  wv2.y, x1);
            ffma2(acc2[0][6],  wv3.x, x0); ffma2(acc2[1][6],  wv3.x, x1);
            ffma2(acc2[0][7],  wv3.y, x0); ffma2(acc2[1][7],  wv3.y, x1);
            ffma2(acc2[0][8],  wv4.x, x0); ffma2(acc2[1][8],  wv4.x, x1);
            ffma2(acc2[0][9],  wv4.y, x0); ffma2(acc2[1][9],  wv4.y, x1);
            ffma2(acc2[0][10], wv5.x, x0); ffma2(acc2[1][10], wv5.x, x1);
            ffma2(acc2[0][11], wv5.y, x0); ffma2(acc2[1][11], wv5.y, x1);
            ffma2(acc2[0][12], wv6.x, x0); ffma2(acc2[1][12], wv6.x, x1);
        }
    }
#pragma unroll
    for (int o2 = 0; o2 < 13; o2++) {
        int ocA = oc0 + 2 * o2;
        float bA = c2b[ocA];
        float bB = (2 * o2 + 1 < 25) ? c2b[ocA + 1] : 0.f;
#pragma unroll
        for (int r = 0; r < 2; r++) {
            float lo, hi;
            unpack2(acc2[r][o2], lo, hi);
            g_wgt[((b * 200 + ocA) * H + (h0 + r)) * W + w0 + px] = lo + bA;
            if (2 * o2 + 1 < 25)
                g_wgt[((b * 200 + ocA + 1) * H + (h0 + r)) * W + w0 + px] = hi + bB;
        }
    }
}

// ---------------- K4: involution + out conv + BN + leaky (R15 proven) ----------------
#define K4_SMEM 78592
extern __shared__ char k4s[];
__global__ void __launch_bounds__(256) k4_out(float* __restrict__ out) {
    u64   (*c2)[8][5][36] = (u64 (*)[8][5][36])k4s;
    float (*w2)[25][32]   = (float (*)[25][32])(k4s + 23040);
    float (*o_s)[32]      = (float (*)[32])(k4s + 29440);
    float (*ow_s)[64]     = (float (*)[64])(k4s + 45824);

    int blk = blockIdx.x;
    int q   = blk & 3;
    int h   = (blk >> 2) & 127;
    int b   = blk >> 9;
    int w0  = q * 32;

    int t  = threadIdx.x;
    int px = t & 31;
    int tg = t >> 5;

    {
        u32 owsm = smem_u32(k4s) + 45824;
#pragma unroll
        for (int j = 0; j < 8; j++) {
            int e = t + j * 256;
            cp16(owsm + e * 16, g_owT + e * 4);
        }
        cp_commit();
    }

    int ccA = t / 36,         colA = t % 36;
    int ccB = (t + 256) / 36, colB = (t + 256) % 36;
    bool hasB = (t < 32);
    int wwA = w0 - 2 + colA;  bool okA = (wwA >= 0) && (wwA < W);
    int wwB = w0 - 2 + colB;  bool okB = (wwB >= 0) && (wwB < W);
    bool hasW3 = (t < 32);

    float pa[5][2], pb[5][2], pw[4];

    {
        const float* baseA = &g_cat[(b * 128 + ccA) * HW + wwA];
#pragma unroll
        for (int rr = 0; rr < 5; rr++) {
            int hh = h - 2 + rr;
            bool ok = okA && hh >= 0 && hh < H;
            pa[rr][0] = ok ? baseA[hh * W] : 0.f;
            pa[rr][1] = ok ? baseA[8 * HW + hh * W] : 0.f;
        }
        if (hasB) {
            const float* baseB = &g_cat[(b * 128 + ccB) * HW + wwB];
#pragma unroll
            for (int rr = 0; rr < 5; rr++) {
                int hh = h - 2 + rr;
                bool ok = okB && hh >= 0 && hh < H;
                pb[rr][0] = ok ? baseB[hh * W] : 0.f;
                pb[rr][1] = ok ? baseB[8 * HW + hh * W] : 0.f;
            }
        }
        const float* wbase = &g_wgt[((u64)(b * 200) * H + h) * W + w0];
#pragma unroll
        for (int j = 0; j < 3; j++) {
            int i = t + j * 256;
            pw[j] = wbase[(u64)(i >> 5) * HW + (i & 31)];
        }
        if (hasW3) {
            int i = t + 768;
            pw[3] = wbase[(u64)(i >> 5) * HW + (i & 31)];
        }
#pragma unroll
        for (int rr = 0; rr < 5; rr++) c2[0][ccA][rr][colA] = pack2(pa[rr][0], pa[rr][1]);
        if (hasB)
#pragma unroll
            for (int rr = 0; rr < 5; rr++) c2[0][ccB][rr][colB] = pack2(pb[rr][0], pb[rr][1]);
#pragma unroll
        for (int j = 0; j < 3; j++) {
            int i = t + j * 256;
            w2[0][i >> 5][i & 31] = pw[j];
        }
        if (hasW3) {
            int i = t + 768;
            w2[0][i >> 5][i & 31] = pw[3];
        }
    }

    for (int g = 0; g < 8; g++) {
        __syncthreads();
        if (g < 7) {
            int gc = (g + 1) * 16;
            const float* baseA = &g_cat[(b * 128 + gc + ccA) * HW + wwA];
#pragma unroll
            for (int rr = 0; rr < 5; rr++) {
                int hh = h - 2 + rr;
                bool ok = okA && hh >= 0 && hh < H;
                pa[rr][0] = ok ? baseA[hh * W] : 0.f;
                pa[rr][1] = ok ? baseA[8 * HW + hh * W] : 0.f;
            }
            if (hasB) {
                const float* baseB = &g_cat[(b * 128 + gc + ccB) * HW + wwB];
#pragma unroll
                for (int rr = 0; rr < 5; rr++) {
                    int hh = h - 2 + rr;
                    bool ok = okB && hh >= 0 && hh < H;
                    pb[rr][0] = ok ? baseB[hh * W] : 0.f;
                    pb[rr][1] = ok ? baseB[8 * HW + hh * W] : 0.f;
                }
            }
            const float* wbase = &g_wgt[((u64)(b * 200 + (g + 1) * 25) * H + h) * W + w0];
#pragma unroll
            for (int j = 0; j < 3; j++) {
                int i = t + j * 256;
                pw[j] = wbase[(u64)(i >> 5) * HW + (i & 31)];
            }
            if (hasW3) {
                int i = t + 768;
                pw[3] = wbase[(u64)(i >> 5) * HW + (i & 31)];
            }
        }
        int cb = g & 1;
        u64 a = 0ull;
#pragma unroll
        for (int i = 0; i < 5; i++)
#pragma unroll
            for (int j = 0; j < 5; j++) {
                u64 wv = dup2(w2[cb][i * 5 + j][px]);
                ffma2(a, c2[cb][tg][i][px + j], wv);
            }
        float lo, hi;
        unpack2(a, lo, hi);
        o_s[g * 16 + tg][px]     = lo;
        o_s[g * 16 + tg + 8][px] = hi;
        if (g < 7) {
            int nb = (g + 1) & 1;
#pragma unroll
            for (int rr = 0; rr < 5; rr++) c2[nb][ccA][rr][colA] = pack2(pa[rr][0], pa[rr][1]);
            if (hasB)
#pragma unroll
                for (int rr = 0; rr < 5; rr++) c2[nb][ccB][rr][colB] = pack2(pb[rr][0], pb[rr][1]);
#pragma unroll
            for (int j = 0; j < 3; j++) {
                int i = t + j * 256;
                w2[nb][i >> 5][i & 31] = pw[j];
            }
            if (hasW3) {
                int i = t + 768;
                w2[nb][i >> 5][i & 31] = pw[3];
            }
        }
    }
    cp_wait0();
    __syncthreads();

    int oc0 = tg * 8;
    u64 acc2[4] = {0ull, 0ull, 0ull, 0ull};
#pragma unroll 4
    for (int c = 0; c < 128; c++) {
        u64 od = dup2(o_s[c][px]);
        ulonglong2 wa = *(const ulonglong2*)&ow_s[c][oc0];
        ulonglong2 wb = *(const ulonglong2*)&ow_s[c][oc0 + 4];
        ffma2(acc2[0], wa.x, od);
        ffma2(acc2[1], wa.y, od);
        ffma2(acc2[2], wb.x, od);
        ffma2(acc2[3], wb.y, od);
    }
#pragma unroll
    for (int i = 0; i < 4; i++) {
        float lo, hi;
        unpack2(acc2[i], lo, hi);
        int ocA = oc0 + 2 * i, ocB = ocA + 1;
        float yA = lo * g_bns[ocA] + g_bnb[ocA];
        float yB = hi * g_bns[ocB] + g_bnb[ocB];
        yA = yA > 0.f ? yA : 0.01f * yA;
        yB = yB > 0.f ? yB : 0.01f * yB;
        out[((b * 64 + ocA) * H + h) * W + w0 + px] = yA;
        out[((b * 64 + ocB) * H + h) * W + w0 + px] = yB;
    }
}

// ---------------- launch ----------------
extern "C" void kernel_launch(void* const* d_in, const int* in_sizes, int n_in,
                              void* d_out, int out_size) {
    const float* hi        = (const float*)d_in[0];
    const float* lo        = (const float*)d_in[1];
    const float* emb       = (const float*)d_in[2];
    const float* reduce_w  = (const float*)d_in[3];
    const float* reduce_b  = (const float*)d_in[4];
    const float* conv1_w   = (const float*)d_in[5];
    const float* conv1_b   = (const float*)d_in[6];
    const float* conv2_w   = (const float*)d_in[7];
    const float* conv2_b   = (const float*)d_in[8];
    const float* embconv_w = (const float*)d_in[9];
    const float* embconv_b = (const float*)d_in[10];
    const float* out_w     = (const float*)d_in[11];
    const float* out_b     = (const float*)d_in[12];
    const float* bn_gamma  = (const float*)d_in[13];
    const float* bn_beta   = (const float*)d_in[14];
    const float* bn_mean   = (const float*)d_in[15];
    const float* bn_var    = (const float*)d_in[16];
    float* out = (float*)d_out;

    cudaFuncSetAttribute(k3_conv2, cudaFuncAttributeMaxDynamicSharedMemorySize, K3_SMEM);
    cudaFuncSetAttribute(k4_out,   cudaFuncAttributeMaxDynamicSharedMemorySize, K4_SMEM);

    prep_kernel<<<128, 256>>>(reduce_w, conv1_w, conv1_b, embconv_w, embconv_b,
                              conv2_w, out_w, out_b, bn_gamma, bn_beta, bn_mean, bn_var);
    k1_cat<<<(BATCH * HW) / 64, 256>>>(hi, lo, reduce_b);
    k2_mix<<<BATCH * H, 256>>>(emb);
    k3_conv2<<<BATCH * (H / 2) * 4, 256, K3_SMEM>>>(conv2_b);
    k4_out<<<BATCH * H * 4, 256, K4_SMEM>>>(out);
}